// round 17
// baseline (speedup 1.0000x reference)
#include <cuda_runtime.h>

#define CB 32
#define CT 1024
#define CV 1024
#define CL 100
#define CS 201           // 2*L+1
#define SP 224           // 32 lanes * 7 states (permuted layout)
#define NK 7             // states per lane
#define LOG2E 1.4426950408889634f
#define LN2F  0.6931471805599453f
#define FULLM 0xffffffffu

// Scratch: softmax PROBABILITIES of extended labels, lane-permuted
// (validated layout): [B][T][slot], slot = l + 32*k holds state s = 7*l + k.
__device__ float g_lp[(size_t)CB * CT * SP];
__device__ float g_loss[CB];

// ---------------------------------------------------------------------------
// Kernel 1: warp-per-row softmax + gather of extended-label PROBABILITIES.
// (Unchanged from R16 — validated.)
// ---------------------------------------------------------------------------
__global__ void __launch_bounds__(256) prob_gather_kernel(
    const float* __restrict__ logits, const int* __restrict__ targets)
{
    const int lane = threadIdx.x & 31;
    const int w    = threadIdx.x >> 5;
    const int t    = blockIdx.x * 8 + w;
    const int b    = blockIdx.y;
    const float* __restrict__ row = logits + ((size_t)b * CT + t) * CV;
    const int* __restrict__ tg = targets + b * CL;

    const float4* r4 = reinterpret_cast<const float4*>(row);
    float4 v[8];
    #pragma unroll
    for (int i = 0; i < 8; i++) v[i] = r4[lane + 32 * i];

    float m = -3.4e38f;
    #pragma unroll
    for (int i = 0; i < 8; i++)
        m = fmaxf(m, fmaxf(fmaxf(v[i].x, v[i].y), fmaxf(v[i].z, v[i].w)));
    #pragma unroll
    for (int o = 16; o > 0; o >>= 1) m = fmaxf(m, __shfl_xor_sync(FULLM, m, o));

    float s0 = 0.f, s1 = 0.f, s2 = 0.f, s3 = 0.f;
    #pragma unroll
    for (int i = 0; i < 8; i++) {
        s0 += exp2f((v[i].x - m) * LOG2E);
        s1 += exp2f((v[i].y - m) * LOG2E);
        s2 += exp2f((v[i].z - m) * LOG2E);
        s3 += exp2f((v[i].w - m) * LOG2E);
    }
    float sum = (s0 + s1) + (s2 + s3);
    #pragma unroll
    for (int o = 16; o > 0; o >>= 1) sum += __shfl_xor_sync(FULLM, sum, o);

    const float lse2 = m * LOG2E + __log2f(sum);

    float* __restrict__ orow = g_lp + ((size_t)b * CT + t) * SP;
    #pragma unroll
    for (int i = 0; i < NK; i++) {
        const int s = NK * lane + i;
        float val = 0.0f;
        if (s < CS) {
            int sym = (s & 1) ? __ldg(&tg[s >> 1]) : (CV - 1);
            val = exp2f(__ldg(row + sym) * LOG2E - lse2);
        }
        orow[lane + 32 * i] = val;
    }
}

// ---------------------------------------------------------------------------
// Probability-domain forward step (R16-validated).
// ---------------------------------------------------------------------------
__device__ __forceinline__ void prob_step(float a[NK], const float p[NK],
                                          const bool sk[NK], int lane,
                                          float hs1, float hs2)
{
    float h1 = __shfl_up_sync(FULLM, a[NK - 1], 1);
    float h2 = __shfl_up_sync(FULLM, a[NK - 2], 1);
    h1 = (h1 * hs1) * hs2;
    h2 = (h2 * hs1) * hs2;
    if (lane == 0) { h1 = 0.f; h2 = 0.f; }
    float n[NK];
    n[0] = (a[0] + h1   + (sk[0] ? h2   : 0.f)) * p[0];
    n[1] = (a[1] + a[0] + (sk[1] ? h1   : 0.f)) * p[1];
    #pragma unroll
    for (int k = 2; k < NK; k++)
        n[k] = (a[k] + a[k - 1] + (sk[k] ? a[k - 2] : 0.f)) * p[k];
    #pragma unroll
    for (int k = 0; k < NK; k++) a[k] = n[k];
}

// ---------------------------------------------------------------------------
// PER-LANE exact power-of-2 renormalization (R16-validated).
// ---------------------------------------------------------------------------
__device__ __forceinline__ void renorm_lane(float a[NK], int& D,
                                            float& hs1, float& hs2)
{
    float m = fmaxf(fmaxf(fmaxf(a[0], a[1]), fmaxf(a[2], a[3])),
                    fmaxf(fmaxf(a[4], a[5]), a[6]));
    const bool z = (m == 0.0f);
    int e  = (int)(__float_as_uint(m) >> 23);
    int sf = z ? 127 : min(max(274 - e, 1), 254);
    float sc = __uint_as_float((unsigned)sf << 23);
    #pragma unroll
    for (int k = 0; k < NK; k++) a[k] *= sc;

    int Dn = D + (sf - 127);
    int Dup = __shfl_up_sync(FULLM, Dn, 1);
    if (z) Dn = Dup;
    D = Dn;

    int Dup2 = __shfl_up_sync(FULLM, Dn, 1);
    int d = Dn - Dup2;
    d = min(max(d, -252), 252);
    int d1 = d >> 1;
    int d2 = d - d1;
    hs1 = __uint_as_float((unsigned)(127 + d1) << 23);
    hs2 = __uint_as_float((unsigned)(127 + d2) << 23);
}

#define PF(buf, base, tt)                                                  \
    _Pragma("unroll")                                                      \
    for (int k = 0; k < NK; k++) buf[k] = (base)[(size_t)(tt) * SP + 32 * k];

// ---------------------------------------------------------------------------
// Kernel 2: forward-only CTC DP, TWO independent batch chains per warp.
// grid = CB/2 CTAs of 32 threads. Chain c handles batch 2*bid + c.
// The two chains' instruction streams interleave, hiding exposed latency.
// ---------------------------------------------------------------------------
__global__ void __launch_bounds__(32, 1) ctc_dp_kernel(const int* __restrict__ targets)
{
    const int b0 = 2 * blockIdx.x;
    const int b1 = b0 + 1;
    const int l  = threadIdx.x;
    const float* __restrict__ lpb0 = g_lp + (size_t)b0 * CT * SP + l;
    const float* __restrict__ lpb1 = g_lp + (size_t)b1 * CT * SP + l;
    const int* __restrict__ tg0 = targets + b0 * CL;
    const int* __restrict__ tg1 = targets + b1 * CL;

    bool sk0[NK], sk1[NK];
    #pragma unroll
    for (int k = 0; k < NK; k++) {
        int s = NK * l + k;
        bool ok = (s & 1) && (s >= 3) && (s < CS);
        int i = min(s >> 1, CL - 1), im = max((s >> 1) - 1, 0);
        sk0[k] = ok && (__ldg(&tg0[i]) != __ldg(&tg0[im]));
        sk1[k] = ok && (__ldg(&tg1[i]) != __ldg(&tg1[im]));
    }

    float a0[NK], bA0[NK], bB0[NK], bC0[NK], bD0[NK];
    float a1[NK], bA1[NK], bB1[NK], bC1[NK], bD1[NK];
    int   D0 = 0, D1 = 0;
    float h01 = 1.f, h02 = 1.f, h11 = 1.f, h12 = 1.f;

    #pragma unroll
    for (int k = 0; k < NK; k++) {
        int s = NK * l + k;
        float v0 = lpb0[32 * k];
        float v1 = lpb1[32 * k];
        a0[k] = (s < 2) ? v0 : 0.f;
        a1[k] = (s < 2) ? v1 : 0.f;
    }
    PF(bA0, lpb0, 1) PF(bB0, lpb0, 2) PF(bC0, lpb0, 3) PF(bD0, lpb0, 4)
    PF(bA1, lpb1, 1) PF(bB1, lpb1, 2) PF(bC1, lpb1, 3) PF(bD1, lpb1, 4)

    #pragma unroll 1
    for (int t = 1; t + 3 <= CT - 4; t += 4) {        // steps 1..1020
        prob_step(a0, bA0, sk0, l, h01, h02);  PF(bA0, lpb0, t + 4)
        prob_step(a1, bA1, sk1, l, h11, h12);  PF(bA1, lpb1, t + 4)
        prob_step(a0, bB0, sk0, l, h01, h02);  PF(bB0, lpb0, t + 5)
        prob_step(a1, bB1, sk1, l, h11, h12);  PF(bB1, lpb1, t + 5)
        prob_step(a0, bC0, sk0, l, h01, h02);  PF(bC0, lpb0, t + 6)
        prob_step(a1, bC1, sk1, l, h11, h12);  PF(bC1, lpb1, t + 6)
        {
            const int tn = (t + 7 < CT) ? (t + 7) : (CT - 1);
            prob_step(a0, bD0, sk0, l, h01, h02);  PF(bD0, lpb0, tn)
            prob_step(a1, bD1, sk1, l, h11, h12);  PF(bD1, lpb1, tn)
        }
        renorm_lane(a0, D0, h01, h02);
        renorm_lane(a1, D1, h11, h12);
    }
    prob_step(a0, bA0, sk0, l, h01, h02);             // step 1021
    prob_step(a1, bA1, sk1, l, h11, h12);
    prob_step(a0, bB0, sk0, l, h01, h02);             // step 1022
    prob_step(a1, bB1, sk1, l, h11, h12);
    prob_step(a0, bC0, sk0, l, h01, h02);             // step 1023
    prob_step(a1, bC1, sk1, l, h11, h12);

    // loss = -ln(alpha[199] + alpha[200]); states 199,200 live in lane 28 (k=3,4).
    if (l == 28) {
        float r0 = a0[3] + a0[4];
        float r1 = a1[3] + a1[4];
        g_loss[b0] = -(__log2f(r0) - (float)D0) * LN2F;
        g_loss[b1] = -(__log2f(r1) - (float)D1) * LN2F;
    }
}

// ---------------------------------------------------------------------------
// Kernel 3: mean over B (one warp).
// ---------------------------------------------------------------------------
__global__ void __launch_bounds__(32) reduce_kernel(float* __restrict__ out)
{
    float v = g_loss[threadIdx.x];
    #pragma unroll
    for (int o = 16; o > 0; o >>= 1) v += __shfl_xor_sync(FULLM, v, o);
    if (threadIdx.x == 0) out[0] = v * (1.0f / CB);
}

extern "C" void kernel_launch(void* const* d_in, const int* in_sizes, int n_in,
                              void* d_out, int out_size)
{
    const int*   targets = (const int*)d_in[0];
    const float* logits  = (const float*)d_in[1];
    float*       out     = (float*)d_out;

    dim3 g1(CT / 8, CB);
    prob_gather_kernel<<<g1, 256>>>(logits, targets);
    ctc_dp_kernel<<<CB / 2, 32>>>(targets);
    reduce_kernel<<<1, 32>>>(out);
}